// round 1
// baseline (speedup 1.0000x reference)
#include <cuda_runtime.h>
#include <math.h>

#define LLEN 8192
#define BATCH 256
#define TL 512
#define EPSB 1e-5f

// Per-batch folded attention matrix: W_eff[b] = diag(inv2) * Wc2 * (beta*A_b + I)
__device__ float g_Weff[BATCH * 256];

// ---------------------------------------------------------------------------
// Kernel 1: per-batch gram of c0, softmax attention, fold into W_eff.
// One block per batch, 256 threads.
// ---------------------------------------------------------------------------
__global__ __launch_bounds__(256) void attn_prep_kernel(
    const float* __restrict__ x,
    const float* __restrict__ wc1, const float* __restrict__ g1,
    const float* __restrict__ bt1, const float* __restrict__ m1,
    const float* __restrict__ v1,
    const float* __restrict__ beta_cam,
    const float* __restrict__ wc2, const float* __restrict__ g2,
    const float* __restrict__ bt2, const float* __restrict__ m2,
    const float* __restrict__ v2)
{
    __shared__ float c0s[16 * 260];   // [c][pos], row stride 260 to dodge bank conflicts
    __shared__ float gsm[256];
    __shared__ float asmem[256];
    __shared__ float u1s[64];
    __shared__ float sh1s[16];

    const int b = blockIdx.x;
    const int t = threadIdx.x;

    if (t < 16) {
        float inv1 = g1[t] / sqrtf(v1[t] + EPSB);
        sh1s[t] = bt1[t] - m1[t] * inv1;
        #pragma unroll
        for (int i = 0; i < 4; i++) u1s[t * 4 + i] = inv1 * wc1[t * 4 + i];
    }
    __syncthreads();

    // hoist weights to registers
    float uw[64];
    float sh[16];
    #pragma unroll
    for (int i = 0; i < 64; i++) uw[i] = u1s[i];
    #pragma unroll
    for (int i = 0; i < 16; i++) sh[i] = sh1s[i];

    const int cg = t >> 4;
    const int dg = t & 15;
    float gacc = 0.f;

    for (int ch = 0; ch < LLEN / 256; ch++) {
        int p = ch * 256 + t;
        float xv0 = x[(b * 4 + 0) * LLEN + p];
        float xv1 = x[(b * 4 + 1) * LLEN + p];
        float xv2 = x[(b * 4 + 2) * LLEN + p];
        float xv3 = x[(b * 4 + 3) * LLEN + p];
        __syncthreads();   // previous phase-2 reads done
        #pragma unroll
        for (int c = 0; c < 16; c++) {
            float v = sh[c] + uw[c * 4 + 0] * xv0 + uw[c * 4 + 1] * xv1
                            + uw[c * 4 + 2] * xv2 + uw[c * 4 + 3] * xv3;
            c0s[c * 260 + t] = fmaxf(v, 0.f);
        }
        __syncthreads();
        const float4* ra = (const float4*)(c0s + cg * 260);
        const float4* rb = (const float4*)(c0s + dg * 260);
        #pragma unroll
        for (int j = 0; j < 64; j++) {
            float4 a = ra[j], bb = rb[j];
            gacc += a.x * bb.x + a.y * bb.y + a.z * bb.z + a.w * bb.w;
        }
    }
    gsm[t] = gacc;
    __syncthreads();

    // softmax over rows of Z = rowmax - G  (thread c handles row c)
    if (t < 16) {
        float rmin = 1e30f;
        #pragma unroll
        for (int d = 0; d < 16; d++) rmin = fminf(rmin, gsm[t * 16 + d]);
        float e[16];
        float s = 0.f;
        #pragma unroll
        for (int d = 0; d < 16; d++) { e[d] = expf(rmin - gsm[t * 16 + d]); s += e[d]; }
        float invs = 1.f / s;
        #pragma unroll
        for (int d = 0; d < 16; d++) asmem[t * 16 + d] = e[d] * invs;
    }
    __syncthreads();

    // W_eff[c][d] = inv2[c] * ( beta * sum_e wc2[c][e]*A[e][d] + wc2[c][d] )
    {
        float inv2c = g2[cg] / sqrtf(v2[cg] + EPSB);
        float beta = beta_cam[0];
        float s = 0.f;
        #pragma unroll
        for (int e = 0; e < 16; e++) s += wc2[cg * 16 + e] * asmem[e * 16 + dg];
        g_Weff[b * 256 + t] = inv2c * (beta * s + wc2[cg * 16 + dg]);
    }
}

// ---------------------------------------------------------------------------
// Kernel 2: fused ConvFusion + attention epilogue.
// Grid (L/TL, B), 256 threads. Per block: 512 output positions, all 16 ch.
// ---------------------------------------------------------------------------
__global__ __launch_bounds__(256) void main_kernel(
    const float* __restrict__ x,
    const float* __restrict__ w00, const float* __restrict__ b00,
    const float* __restrict__ w01, const float* __restrict__ b01,
    const float* __restrict__ w02, const float* __restrict__ b02,
    const float* __restrict__ wc1, const float* __restrict__ g1,
    const float* __restrict__ bt1, const float* __restrict__ m1,
    const float* __restrict__ v1,
    const float* __restrict__ g2, const float* __restrict__ bt2,
    const float* __restrict__ m2, const float* __restrict__ v2,
    float* __restrict__ out)
{
    __shared__ float xs[4 * 580];      // x[l0-32 .. l0+TL+33], zero padded
    __shared__ float f0s[8 * 544];     // fea0 for j in [l0-14, l0+TL+16]
    __shared__ float w00s[1024];       // [d][i][k]
    __shared__ float w01t[1024];       // [d][k][c]
    __shared__ float w02t[1024];       // [d][k][c]
    __shared__ float u1s[64];          // [c][i] (inv1 folded)
    __shared__ float sh1s[16];
    __shared__ float sh2s[16];
    __shared__ float weffs[256];
    __shared__ float b00s[8], b01s[8], b02s[8];

    const int t = threadIdx.x;
    const int l0 = blockIdx.x * TL;
    const int b = blockIdx.y;

    // ---- phase A: weights into SMEM ----
    for (int i = t; i < 1024; i += 256) w00s[i] = w00[i];
    for (int i = t; i < 1024; i += 256) {
        int d = i >> 7, k = (i >> 3) & 15, c = i & 7;
        w01t[i] = w01[(c * 8 + d) * 16 + k];
        w02t[i] = w02[(c * 8 + d) * 16 + k];
    }
    if (t < 64) {
        int c = t >> 2;
        float inv1 = g1[c] / sqrtf(v1[c] + EPSB);
        u1s[t] = inv1 * wc1[t];
    }
    if (t < 16) {
        float inv1 = g1[t] / sqrtf(v1[t] + EPSB);
        sh1s[t] = bt1[t] - m1[t] * inv1;
        float inv2 = g2[t] / sqrtf(v2[t] + EPSB);
        sh2s[t] = bt2[t] - m2[t] * inv2;
    }
    weffs[t] = g_Weff[b * 256 + t];
    if (t < 8) { b00s[t] = b00[t]; b01s[t] = b01[t]; b02s[t] = b02[t]; }

    // ---- phase B: x tile (with halo, zero padded) ----
    for (int idx = t; idx < 4 * 580; idx += 256) {
        int i = idx / 580, o = idx - i * 580;
        int g = l0 - 32 + o;
        xs[idx] = (g >= 0 && g < LLEN) ? x[(b * 4 + i) * LLEN + g] : 0.f;
    }
    __syncthreads();

    // ---- phase C: fea0 into SMEM. warp w owns channel d=w; lane owns 17 pos ----
    {
        const int d = t >> 5;
        const int lane = t & 31;
        const int jj0 = lane * 17;
        float acc[17];
        #pragma unroll
        for (int p = 0; p < 17; p++) acc[p] = 0.f;
        for (int i = 0; i < 4; i++) {
            float xw[48];
            const float* xrow = xs + i * 580 + jj0 + 2;
            #pragma unroll
            for (int m = 0; m < 48; m++) xw[m] = xrow[m];
            const float* wrow = w00s + (d * 4 + i) * 32;
            #pragma unroll
            for (int k = 0; k < 32; k++) {
                float wv = wrow[k];
                #pragma unroll
                for (int p = 0; p < 17; p++) acc[p] += wv * xw[p + k];
            }
        }
        float bv = b00s[d];
        #pragma unroll
        for (int p = 0; p < 17; p++) {
            int jj = jj0 + p;
            int j = l0 - 14 + jj;
            f0s[d * 544 + jj] = (j >= 0 && j <= LLEN) ? (acc[p] + bv) : 0.f;
        }
    }
    __syncthreads();

    // ---- phase D: fea1/fea2 + c0 + folded attention epilogue ----
    {
        float accA[2][8], accB[2][8];
        #pragma unroll
        for (int c = 0; c < 8; c++) {
            accA[0][c] = b01s[c]; accA[1][c] = b01s[c];
            accB[0][c] = b02s[c]; accB[1][c] = b02s[c];
        }
        const int base2 = 2 * t;

        for (int d = 0; d < 8; d++) {
            float win[32];
            const float2* fr = (const float2*)(f0s + d * 544 + base2);
            #pragma unroll
            for (int j2 = 0; j2 < 16; j2++) {
                float2 v = fr[j2];
                win[2 * j2] = v.x; win[2 * j2 + 1] = v.y;
            }
            const float* w1r = w01t + d * 128;
            const float* w2r = w02t + d * 128;
            #pragma unroll
            for (int k = 0; k < 16; k++) {
                float4 a0 = *(const float4*)(w1r + k * 8);
                float4 a1 = *(const float4*)(w1r + k * 8 + 4);
                float4 e0 = *(const float4*)(w2r + k * 8);
                float4 e1 = *(const float4*)(w2r + k * 8 + 4);
                float wA[8] = {a0.x, a0.y, a0.z, a0.w, a1.x, a1.y, a1.z, a1.w};
                float wB[8] = {e0.x, e0.y, e0.z, e0.w, e1.x, e1.y, e1.z, e1.w};
                float fA0 = win[7 + k], fA1 = win[8 + k];
                float fB0 = win[2 * k], fB1 = win[2 * k + 1];
                #pragma unroll
                for (int c = 0; c < 8; c++) {
                    accA[0][c] += wA[c] * fA0;
                    accA[1][c] += wA[c] * fA1;
                    accB[0][c] += wB[c] * fB0;
                    accB[1][c] += wB[c] * fB1;
                }
            }
        }

        // c0 for both positions
        float c0v[2][16];
        #pragma unroll
        for (int p = 0; p < 2; p++) {
            int o = 32 + base2 + p;
            float x0 = xs[0 * 580 + o], x1 = xs[1 * 580 + o];
            float x2 = xs[2 * 580 + o], x3 = xs[3 * 580 + o];
            #pragma unroll
            for (int c = 0; c < 16; c++) {
                float4 u = *(const float4*)(u1s + c * 4);
                float v = sh1s[c] + u.x * x0 + u.y * x1 + u.z * x2 + u.w * x3;
                c0v[p][c] = fmaxf(v, 0.f);
            }
        }

        const int l = l0 + base2;
        #pragma unroll
        for (int c = 0; c < 16; c++) {
            float s0 = sh2s[c], s1 = sh2s[c];
            #pragma unroll
            for (int dq = 0; dq < 16; dq += 4) {
                float4 wv = *(const float4*)(weffs + c * 16 + dq);
                s0 += wv.x * c0v[0][dq] + wv.y * c0v[0][dq + 1]
                    + wv.z * c0v[0][dq + 2] + wv.w * c0v[0][dq + 3];
                s1 += wv.x * c0v[1][dq] + wv.y * c0v[1][dq + 1]
                    + wv.z * c0v[1][dq + 2] + wv.w * c0v[1][dq + 3];
            }
            float f0v, f1v;
            if (c < 8) {
                f0v = accA[0][c]; f1v = accA[1][c];
            } else {
                f0v = accB[0][c - 8]; f1v = accB[1][c - 8];
                // fea2 external zero padding: l==0 and l>=8190 are literal zeros
                if (l == 0 || l >= 8190) f0v = 0.f;
                if (l + 1 >= 8190)       f1v = 0.f;
            }
            float2 ov;
            ov.x = f0v + fmaxf(s0, 0.f);
            ov.y = f1v + fmaxf(s1, 0.f);
            *(float2*)(out + (b * 16 + c) * LLEN + l) = ov;
        }
    }
}

// ---------------------------------------------------------------------------
extern "C" void kernel_launch(void* const* d_in, const int* in_sizes, int n_in,
                              void* d_out, int out_size)
{
    const float* x        = (const float*)d_in[0];
    const float* w00      = (const float*)d_in[1];
    const float* b00      = (const float*)d_in[2];
    const float* w01      = (const float*)d_in[3];
    const float* b01      = (const float*)d_in[4];
    const float* w02      = (const float*)d_in[5];
    const float* b02      = (const float*)d_in[6];
    const float* wc1      = (const float*)d_in[7];
    const float* g1       = (const float*)d_in[8];
    const float* bt1      = (const float*)d_in[9];
    const float* m1       = (const float*)d_in[10];
    const float* v1       = (const float*)d_in[11];
    const float* beta_cam = (const float*)d_in[12];
    const float* wc2      = (const float*)d_in[13];
    const float* g2       = (const float*)d_in[14];
    const float* bt2      = (const float*)d_in[15];
    const float* m2       = (const float*)d_in[16];
    const float* v2       = (const float*)d_in[17];
    float* out = (float*)d_out;

    attn_prep_kernel<<<BATCH, 256>>>(x, wc1, g1, bt1, m1, v1, beta_cam,
                                     wc2, g2, bt2, m2, v2);
    dim3 grid(LLEN / TL, BATCH);
    main_kernel<<<grid, 256>>>(x, w00, b00, w01, b01, w02, b02,
                               wc1, g1, bt1, m1, v1, g2, bt2, m2, v2, out);
}

// round 2
// speedup vs baseline: 1.0177x; 1.0177x over previous
#include <cuda_runtime.h>
#include <math.h>

#define LLEN 8192
#define BATCH 256
#define TL 512
#define EPSB 1e-5f
#define XROW 612
#define FROW 584

typedef unsigned long long u64;

// ---------------- f32x2 helpers (sm_100a packed math) ----------------
__device__ __forceinline__ u64 f2(u64 a, u64 b, u64 c) {
    u64 d;
    asm("fma.rn.f32x2 %0, %1, %2, %3;" : "=l"(d) : "l"(a), "l"(b), "l"(c));
    return d;
}
__device__ __forceinline__ u64 pk(float lo, float hi) {
    u64 d;
    asm("mov.b64 %0, {%1, %2};" : "=l"(d) : "f"(lo), "f"(hi));
    return d;
}
__device__ __forceinline__ float lo2(u64 v) {
    float f;
    asm("{.reg .f32 hi;\n\tmov.b64 {%0, hi}, %1;}" : "=f"(f) : "l"(v));
    return f;
}
__device__ __forceinline__ float hi2(u64 v) {
    float f;
    asm("{.reg .f32 lo;\n\tmov.b64 {lo, %0}, %1;}" : "=f"(f) : "l"(v));
    return f;
}
__device__ __forceinline__ u64 splat_lo(u64 v) {
    u64 d;
    asm("{.reg .f32 a, b;\n\tmov.b64 {a, b}, %1;\n\tmov.b64 %0, {a, a};}"
        : "=l"(d) : "l"(v));
    return d;
}
__device__ __forceinline__ u64 splat_hi(u64 v) {
    u64 d;
    asm("{.reg .f32 a, b;\n\tmov.b64 {a, b}, %1;\n\tmov.b64 %0, {b, b};}"
        : "=l"(d) : "l"(v));
    return d;
}

// ---------------- device scratch ----------------
__device__ float g_gram[BATCH * 256];
__device__ float g_Weff[BATCH * 256];

// ---------------------------------------------------------------------------
// Kernel 0: zero the gram accumulator
// ---------------------------------------------------------------------------
__global__ void zero_gram_kernel() {
    g_gram[blockIdx.x * 256 + threadIdx.x] = 0.f;
}

// ---------------------------------------------------------------------------
// Kernel 1: partial gram of c0, 8 blocks per batch over L, atomicAdd.
// ---------------------------------------------------------------------------
__global__ __launch_bounds__(256) void gram_partial_kernel(
    const float* __restrict__ x,
    const float* __restrict__ wc1, const float* __restrict__ g1,
    const float* __restrict__ bt1, const float* __restrict__ m1,
    const float* __restrict__ v1)
{
    __shared__ float c0s[16 * 260];
    __shared__ float u1s[64];
    __shared__ float sh1s[16];

    const int b = blockIdx.y;
    const int chunk = blockIdx.x;
    const int t = threadIdx.x;

    if (t < 16) {
        float inv1 = g1[t] * rsqrtf(v1[t] + EPSB);
        sh1s[t] = bt1[t] - m1[t] * inv1;
        #pragma unroll
        for (int i = 0; i < 4; i++) u1s[t * 4 + i] = inv1 * wc1[t * 4 + i];
    }
    __syncthreads();

    float uw[64], sh[16];
    #pragma unroll
    for (int i = 0; i < 64; i++) uw[i] = u1s[i];
    #pragma unroll
    for (int i = 0; i < 16; i++) sh[i] = sh1s[i];

    const int cg = t >> 4;
    const int dg = t & 15;
    float gacc = 0.f;

    for (int ch = 0; ch < 4; ch++) {
        int p = (chunk * 4 + ch) * 256 + t;
        float xv0 = x[(b * 4 + 0) * LLEN + p];
        float xv1 = x[(b * 4 + 1) * LLEN + p];
        float xv2 = x[(b * 4 + 2) * LLEN + p];
        float xv3 = x[(b * 4 + 3) * LLEN + p];
        __syncthreads();
        #pragma unroll
        for (int c = 0; c < 16; c++) {
            float v = sh[c] + uw[c * 4 + 0] * xv0 + uw[c * 4 + 1] * xv1
                            + uw[c * 4 + 2] * xv2 + uw[c * 4 + 3] * xv3;
            c0s[c * 260 + t] = fmaxf(v, 0.f);
        }
        __syncthreads();
        const float4* ra = (const float4*)(c0s + cg * 260);
        const float4* rb = (const float4*)(c0s + dg * 260);
        #pragma unroll
        for (int j = 0; j < 64; j++) {
            float4 a = ra[j], bb = rb[j];
            gacc += a.x * bb.x + a.y * bb.y + a.z * bb.z + a.w * bb.w;
        }
    }
    atomicAdd(&g_gram[b * 256 + t], gacc);
}

// ---------------------------------------------------------------------------
// Kernel 2: softmax + fold into W_eff
// ---------------------------------------------------------------------------
__global__ __launch_bounds__(256) void fold_kernel(
    const float* __restrict__ beta_cam,
    const float* __restrict__ wc2, const float* __restrict__ g2,
    const float* __restrict__ v2)
{
    __shared__ float gsm[256];
    __shared__ float asmem[256];
    const int b = blockIdx.x;
    const int t = threadIdx.x;

    gsm[t] = g_gram[b * 256 + t];
    __syncthreads();

    if (t < 16) {
        float rmin = 1e30f;
        #pragma unroll
        for (int d = 0; d < 16; d++) rmin = fminf(rmin, gsm[t * 16 + d]);
        float e[16];
        float s = 0.f;
        #pragma unroll
        for (int d = 0; d < 16; d++) { e[d] = expf(rmin - gsm[t * 16 + d]); s += e[d]; }
        float invs = 1.f / s;
        #pragma unroll
        for (int d = 0; d < 16; d++) asmem[t * 16 + d] = e[d] * invs;
    }
    __syncthreads();

    const int cg = t >> 4;
    const int dg = t & 15;
    float inv2c = g2[cg] * rsqrtf(v2[cg] + EPSB);
    float beta = beta_cam[0];
    float s = 0.f;
    #pragma unroll
    for (int e = 0; e < 16; e++) s += wc2[cg * 16 + e] * asmem[e * 16 + dg];
    g_Weff[b * 256 + t] = inv2c * (beta * s + wc2[cg * 16 + dg]);
}

// ---------------------------------------------------------------------------
// Kernel 3: fused ConvFusion + attention epilogue, f32x2 packed.
// Dynamic SMEM layout (floats):
//   xs    [0, 2448)        4 rows x 612
//   xs1   [2448, 4896)     x shifted by +1
//   f0s   [4896, 9568)     8 rows x 584
//   w01t  [9568, 10592)
//   w02t  [10592, 11616)
//   b00s/b01s/b02s [11616, 11640)
//   w00d2 (u64) [11640, 13688)   dup pairs
//   u1d2  (u64) [13688, 13816)
//   sh1d2 (u64) [13816, 13848)
//   sh2d2 (u64) [13848, 13880)
//   weffd2(u64) [13880, 14392)
// total = 14392 floats = 57568 B
// ---------------------------------------------------------------------------
#define SMEM_FLOATS 14392

__global__ __launch_bounds__(256) void main_kernel(
    const float* __restrict__ x,
    const float* __restrict__ w00, const float* __restrict__ b00,
    const float* __restrict__ w01, const float* __restrict__ b01,
    const float* __restrict__ w02, const float* __restrict__ b02,
    const float* __restrict__ wc1, const float* __restrict__ g1,
    const float* __restrict__ bt1, const float* __restrict__ m1,
    const float* __restrict__ v1,
    const float* __restrict__ g2, const float* __restrict__ bt2,
    const float* __restrict__ m2, const float* __restrict__ v2,
    float* __restrict__ out)
{
    extern __shared__ float sm[];
    float* xs    = sm;
    float* xs1   = sm + 2448;
    float* f0s   = sm + 4896;
    float* w01t  = sm + 9568;
    float* w02t  = sm + 10592;
    float* b00s  = sm + 11616;
    float* b01s  = sm + 11624;
    float* b02s  = sm + 11632;
    u64* w00d2   = (u64*)(sm + 11640);
    u64* u1d2    = (u64*)(sm + 13688);
    u64* sh1d2   = (u64*)(sm + 13816);
    u64* sh2d2   = (u64*)(sm + 13848);
    u64* weffd2  = (u64*)(sm + 13880);

    const int t = threadIdx.x;
    const int l0 = blockIdx.x * TL;
    const int b = blockIdx.y;

    // ---- phase A: weights ----
    for (int i = t; i < 1024; i += 256) {
        float wv = w00[i];
        w00d2[i] = pk(wv, wv);
        int d = i >> 7, k = (i >> 3) & 15, c = i & 7;
        w01t[i] = w01[(c * 8 + d) * 16 + k];
        w02t[i] = w02[(c * 8 + d) * 16 + k];
    }
    if (t < 64) {
        int c = t >> 2;
        float inv1 = g1[c] * rsqrtf(v1[c] + EPSB);
        float uv = inv1 * wc1[t];
        u1d2[t] = pk(uv, uv);
    }
    if (t < 16) {
        float inv1 = g1[t] * rsqrtf(v1[t] + EPSB);
        float s1 = bt1[t] - m1[t] * inv1;
        sh1d2[t] = pk(s1, s1);
        float inv2 = g2[t] * rsqrtf(v2[t] + EPSB);
        float s2 = bt2[t] - m2[t] * inv2;
        sh2d2[t] = pk(s2, s2);
    }
    {
        float wv = g_Weff[b * 256 + t];
        weffd2[t] = pk(wv, wv);
    }
    if (t < 8) { b00s[t] = b00[t]; b01s[t] = b01[t]; b02s[t] = b02[t]; }

    // ---- phase B: x tiles (plain + shift-by-one copy) ----
    for (int idx = t; idx < 4 * XROW; idx += 256) {
        int i = idx / XROW, o = idx - i * XROW;
        int g = l0 - 32 + o;
        xs[idx] = (g >= 0 && g < LLEN) ? x[(b * 4 + i) * LLEN + g] : 0.f;
    }
    for (int idx = t; idx < 4 * XROW; idx += 256) {
        int i = idx / XROW, o = idx - i * XROW;
        int g = l0 - 31 + o;
        xs1[idx] = (g >= 0 && g < LLEN) ? x[(b * 4 + i) * LLEN + g] : 0.f;
    }
    __syncthreads();

    // ---- phase C: fea0, packed pairs. warp d, lane covers 18 positions ----
    {
        const int d = t >> 5;
        const int lane = t & 31;
        const int jj0 = lane * 18;
        const int off = jj0 + 2;

        u64 acc[9];
        {
            float bv = b00s[d];
            u64 b2 = pk(bv, bv);
            #pragma unroll
            for (int q = 0; q < 9; q++) acc[q] = b2;
        }

        for (int i = 0; i < 4; i++) {
            const u64* Ep = (const u64*)(xs + i * XROW + off);
            const u64* Op = (const u64*)(xs1 + i * XROW + off);
            const u64* wd = w00d2 + (d * 4 + i) * 32;
            u64 E[9], O[9];
            #pragma unroll
            for (int q = 0; q < 9; q++) { E[q] = Ep[q]; O[q] = Op[q]; }
            #pragma unroll
            for (int m = 0; m < 16; m++) {
                if (m > 0) {
                    E[(m + 8) % 9] = Ep[m + 8];
                    O[(m + 8) % 9] = Op[m + 8];
                }
                u64 wE = wd[2 * m];
                u64 wO = wd[2 * m + 1];
                #pragma unroll
                for (int q = 0; q < 9; q++) acc[q] = f2(wE, E[(m + q) % 9], acc[q]);
                #pragma unroll
                for (int q = 0; q < 9; q++) acc[q] = f2(wO, O[(m + q) % 9], acc[q]);
            }
        }
        // store with fea0 boundary zeroing (valid j in [0, LLEN])
        #pragma unroll
        for (int q = 0; q < 9; q++) {
            int jj = jj0 + 2 * q;
            int j = l0 - 14 + jj;
            float vlo = lo2(acc[q]);
            float vhi = hi2(acc[q]);
            if (j < 0 || j > LLEN) vlo = 0.f;
            if (j + 1 < 0 || j + 1 > LLEN) vhi = 0.f;
            *(u64*)(f0s + d * FROW + jj) = pk(vlo, vhi);
        }
    }
    __syncthreads();

    // ---- phase D: fea1/fea2, packed over channel-pairs ----
    const int base2 = 2 * t;
    u64 aA0[4], aA1[4], aB0[4], aB1[4];
    #pragma unroll
    for (int c2 = 0; c2 < 4; c2++) {
        u64 bA = *(const u64*)(b01s + 2 * c2);
        u64 bB = *(const u64*)(b02s + 2 * c2);
        aA0[c2] = bA; aA1[c2] = bA;
        aB0[c2] = bB; aB1[c2] = bB;
    }

    for (int d = 0; d < 8; d++) {
        const u64* fr = (const u64*)(f0s + d * FROW + base2);
        u64 winp[16];
        #pragma unroll
        for (int j = 0; j < 16; j++) winp[j] = fr[j];
        const longlong2* w1r = (const longlong2*)(w01t + d * 128);
        const longlong2* w2r = (const longlong2*)(w02t + d * 128);
        #pragma unroll
        for (int k = 0; k < 16; k++) {
            u64 fb0 = splat_lo(winp[k]);
            u64 fb1 = splat_hi(winp[k]);
            u64 fa0, fa1;
            if (k & 1) {
                fa0 = splat_lo(winp[(7 + k) >> 1]);
                fa1 = splat_hi(winp[(7 + k) >> 1]);
            } else {
                fa0 = splat_hi(winp[(6 + k) >> 1]);
                fa1 = splat_lo(winp[(8 + k) >> 1]);
            }
            longlong2 wa0 = w1r[2 * k], wa1 = w1r[2 * k + 1];
            longlong2 wb0 = w2r[2 * k], wb1 = w2r[2 * k + 1];
            aA0[0] = f2((u64)wa0.x, fa0, aA0[0]);
            aA0[1] = f2((u64)wa0.y, fa0, aA0[1]);
            aA0[2] = f2((u64)wa1.x, fa0, aA0[2]);
            aA0[3] = f2((u64)wa1.y, fa0, aA0[3]);
            aA1[0] = f2((u64)wa0.x, fa1, aA1[0]);
            aA1[1] = f2((u64)wa0.y, fa1, aA1[1]);
            aA1[2] = f2((u64)wa1.x, fa1, aA1[2]);
            aA1[3] = f2((u64)wa1.y, fa1, aA1[3]);
            aB0[0] = f2((u64)wb0.x, fb0, aB0[0]);
            aB0[1] = f2((u64)wb0.y, fb0, aB0[1]);
            aB0[2] = f2((u64)wb1.x, fb0, aB0[2]);
            aB0[3] = f2((u64)wb1.y, fb0, aB0[3]);
            aB1[0] = f2((u64)wb0.x, fb1, aB1[0]);
            aB1[1] = f2((u64)wb0.y, fb1, aB1[1]);
            aB1[2] = f2((u64)wb1.x, fb1, aB1[2]);
            aB1[3] = f2((u64)wb1.y, fb1, aB1[3]);
        }
    }

    // ---- epilogue: c0 (packed over positions) + folded attention ----
    u64 xp[4];
    #pragma unroll
    for (int i = 0; i < 4; i++)
        xp[i] = *(const u64*)(xs + i * XROW + 32 + base2);

    u64 c0p[16];
    #pragma unroll
    for (int c = 0; c < 16; c++) {
        u64 s = sh1d2[c];
        #pragma unroll
        for (int i = 0; i < 4; i++) s = f2(u1d2[c * 4 + i], xp[i], s);
        c0p[c] = pk(fmaxf(lo2(s), 0.f), fmaxf(hi2(s), 0.f));
    }

    const int l = l0 + base2;
    #pragma unroll
    for (int c = 0; c < 16; c++) {
        u64 s = sh2d2[c];
        #pragma unroll
        for (int dd = 0; dd < 16; dd++) s = f2(weffd2[c * 16 + dd], c0p[dd], s);
        float r0 = fmaxf(lo2(s), 0.f);
        float r1 = fmaxf(hi2(s), 0.f);
        float f0v, f1v;
        if (c < 8) {
            int c2 = c >> 1;
            f0v = (c & 1) ? hi2(aA0[c2]) : lo2(aA0[c2]);
            f1v = (c & 1) ? hi2(aA1[c2]) : lo2(aA1[c2]);
        } else {
            int c2 = (c - 8) >> 1;
            f0v = (c & 1) ? hi2(aB0[c2]) : lo2(aB0[c2]);
            f1v = (c & 1) ? hi2(aB1[c2]) : lo2(aB1[c2]);
            if (l == 0 || l >= LLEN - 2) f0v = 0.f;
            if (l + 1 >= LLEN - 2) f1v = 0.f;
        }
        *(float2*)(out + (b * 16 + c) * LLEN + l) = make_float2(f0v + r0, f1v + r1);
    }
}

// ---------------------------------------------------------------------------
extern "C" void kernel_launch(void* const* d_in, const int* in_sizes, int n_in,
                              void* d_out, int out_size)
{
    const float* x        = (const float*)d_in[0];
    const float* w00      = (const float*)d_in[1];
    const float* b00      = (const float*)d_in[2];
    const float* w01      = (const float*)d_in[3];
    const float* b01      = (const float*)d_in[4];
    const float* w02      = (const float*)d_in[5];
    const float* b02      = (const float*)d_in[6];
    const float* wc1      = (const float*)d_in[7];
    const float* g1       = (const float*)d_in[8];
    const float* bt1      = (const float*)d_in[9];
    const float* m1       = (const float*)d_in[10];
    const float* v1       = (const float*)d_in[11];
    const float* beta_cam = (const float*)d_in[12];
    const float* wc2      = (const float*)d_in[13];
    const float* g2       = (const float*)d_in[14];
    const float* bt2      = (const float*)d_in[15];
    const float* m2       = (const float*)d_in[16];
    const float* v2       = (const float*)d_in[17];
    float* out = (float*)d_out;

    static int smem_set = 0;
    if (!smem_set) {
        cudaFuncSetAttribute(main_kernel,
                             cudaFuncAttributeMaxDynamicSharedMemorySize,
                             SMEM_FLOATS * 4);
        smem_set = 1;
    }

    zero_gram_kernel<<<256, 256>>>();
    dim3 ggrid(8, BATCH);
    gram_partial_kernel<<<ggrid, 256>>>(x, wc1, g1, bt1, m1, v1);
    fold_kernel<<<BATCH, 256>>>(beta_cam, wc2, g2, v2);
    dim3 grid(LLEN / TL, BATCH);
    main_kernel<<<grid, 256, SMEM_FLOATS * 4>>>(
        x, w00, b00, w01, b01, w02, b02,
        wc1, g1, bt1, m1, v1, g2, bt2, m2, v2, out);
}